// round 1
// baseline (speedup 1.0000x reference)
#include <cuda_runtime.h>

// Problem constants (fixed shapes for this problem)
#define MM   20000      // graph nodes
#define NN   16         // batch
#define FINC 64         // input features
#define FOUTC 64        // output features
#define KK   6          // Chebyshev order
#define NNZC 160000     // sparse entries
#define FTOT 1024       // FINC * NN (width of the dense SpMM operand)

// ---------------- device scratch (static, no runtime allocation) ----------------
__device__ int   g_cnt[MM];
__device__ int   g_rowptr[MM + 1];
__device__ int   g_cursor[MM];
__device__ int   g_cols[NNZC];
__device__ float g_vals[NNZC];
// 3 rolling Chebyshev term buffers [M, FTOT] fp32 (80 MB each)
__device__ __align__(16) float g_buf[3][(size_t)MM * FTOT];

// ---------------- CSR build ----------------
__global__ void zero_cnt_kernel() {
    int i = blockIdx.x * blockDim.x + threadIdx.x;
    if (i < MM) g_cnt[i] = 0;
}

__global__ void count_kernel(const int* __restrict__ rows) {
    int i = blockIdx.x * blockDim.x + threadIdx.x;
    if (i < NNZC) atomicAdd(&g_cnt[rows[i]], 1);
}

// single-block exclusive scan over MM counts -> row_ptr, cursor
__global__ void scan_kernel() {
    __shared__ int s[1024];
    int t = threadIdx.x;
    int carry = 0;
    for (int base = 0; base < MM; base += 1024) {
        int idx = base + t;
        int v = (idx < MM) ? g_cnt[idx] : 0;
        s[t] = v;
        __syncthreads();
        // Hillis-Steele inclusive scan
        #pragma unroll
        for (int off = 1; off < 1024; off <<= 1) {
            int tmp = (t >= off) ? s[t - off] : 0;
            __syncthreads();
            s[t] += tmp;
            __syncthreads();
        }
        int inc = s[t];
        int excl = carry + inc - v;
        if (idx < MM) {
            g_rowptr[idx] = excl;
            g_cursor[idx] = excl;
        }
        carry += s[1023];
        __syncthreads();
    }
    if (t == 0) g_rowptr[MM] = carry;
}

__global__ void scatter_kernel(const int* __restrict__ rows,
                               const int* __restrict__ cols,
                               const float* __restrict__ vals) {
    int i = blockIdx.x * blockDim.x + threadIdx.x;
    if (i < NNZC) {
        int r = rows[i];
        int p = atomicAdd(&g_cursor[r], 1);
        g_cols[p] = cols[i];
        g_vals[p] = vals[i];
    }
}

// ---------------- fused GEMM epilogue ----------------
// smem_x layout: [n*64 + fin] (n in 0..15, fin in 0..63)
// smem_w layout: [fin*64 + fo]  (= W[(fin*KK + k)*64 + fo])
// Each thread computes 4 consecutive fo for one n:
//   out[n, m, fo] (+)= sum_fin smem_x[n*64+fin] * smem_w[fin*64+fo]
__device__ __forceinline__ void gemm_epilogue(const float* __restrict__ smem_x,
                                              const float* __restrict__ smem_w,
                                              int m, int t,
                                              const float* __restrict__ bias,
                                              float* __restrict__ out,
                                              bool init) {
    int o0  = t * 4;
    int n   = o0 >> 6;
    int fo0 = o0 & 63;
    float4 r = make_float4(0.f, 0.f, 0.f, 0.f);
    const float* xp = smem_x + n * 64;
    #pragma unroll
    for (int fin = 0; fin < 64; fin += 4) {
        float4 xv = *(const float4*)(xp + fin);
        #pragma unroll
        for (int ff = 0; ff < 4; ++ff) {
            float xs = (ff == 0) ? xv.x : (ff == 1) ? xv.y : (ff == 2) ? xv.z : xv.w;
            float4 wv = *(const float4*)(smem_w + (fin + ff) * 64 + fo0);
            r.x += xs * wv.x;
            r.y += xs * wv.y;
            r.z += xs * wv.z;
            r.w += xs * wv.w;
        }
    }
    float* op = out + ((size_t)n * MM + m) * 64 + fo0;
    if (init) {
        r.x += bias[fo0 + 0];
        r.y += bias[fo0 + 1];
        r.z += bias[fo0 + 2];
        r.w += bias[fo0 + 3];
        *(float4*)op = r;
    } else {
        float4 o = *(const float4*)op;
        r.x += o.x; r.y += o.y; r.z += o.z; r.w += o.w;
        *(float4*)op = r;
    }
}

// stage a term row value c -> smem_x[(c&15)*64 + (c>>4)]
__device__ __forceinline__ void stage_row(float* __restrict__ smem_x, int c0,
                                          float4 acc) {
    int fin = c0 >> 4;  // constant across the 4 consecutive c's
    smem_x[((c0 + 0) & 15) * 64 + fin] = acc.x;
    smem_x[((c0 + 1) & 15) * 64 + fin] = acc.y;
    smem_x[((c0 + 2) & 15) * 64 + fin] = acc.z;
    smem_x[((c0 + 3) & 15) * 64 + fin] = acc.w;
}

// ---------------- k = 0: build x0 from x + GEMM(k=0) + bias init ----------------
__global__ void __launch_bounds__(256) x0_kernel(const float* __restrict__ x,
                                                 const float* __restrict__ W,
                                                 const float* __restrict__ bias,
                                                 float* __restrict__ out) {
    __shared__ float s_x[FTOT];
    __shared__ float s_w[4096];
    int m = blockIdx.x;
    int t = threadIdx.x;

    for (int e = t; e < 4096; e += 256)
        s_w[e] = W[((e >> 6) * KK + 0) * FOUTC + (e & 63)];

    int c0  = t * 4;
    int fin = c0 >> 4;
    float4 acc;
    {
        float v0 = x[((size_t)((c0 + 0) & 15) * MM + m) * FINC + fin];
        float v1 = x[((size_t)((c0 + 1) & 15) * MM + m) * FINC + fin];
        float v2 = x[((size_t)((c0 + 2) & 15) * MM + m) * FINC + fin];
        float v3 = x[((size_t)((c0 + 3) & 15) * MM + m) * FINC + fin];
        acc = make_float4(v0, v1, v2, v3);
    }
    *(float4*)(g_buf[0] + (size_t)m * FTOT + c0) = acc;
    stage_row(s_x, c0, acc);
    __syncthreads();
    gemm_epilogue(s_x, s_w, m, t, bias, out, /*init=*/true);
}

// ---------------- k >= 1: SpMM + recurrence + GEMM(k) accumulate ----------------
__global__ void __launch_bounds__(256) term_kernel(int srcI, int dstI, int p2I,
                                                   int k,
                                                   const float* __restrict__ W,
                                                   float* __restrict__ out) {
    __shared__ float s_x[FTOT];
    __shared__ float s_w[4096];
    __shared__ int   s_col[256];
    __shared__ float s_val[256];
    int m = blockIdx.x;
    int t = threadIdx.x;

    const float* Tsrc = g_buf[srcI];
    float*       Tdst = g_buf[dstI];

    for (int e = t; e < 4096; e += 256)
        s_w[e] = W[((e >> 6) * KK + k) * FOUTC + (e & 63)];

    int start = g_rowptr[m];
    int end   = g_rowptr[m + 1];

    float4 acc = make_float4(0.f, 0.f, 0.f, 0.f);
    int c0 = t * 4;

    for (int cb = start; cb < end; cb += 256) {
        int j = cb + t;
        if (j < end) {
            s_col[t] = g_cols[j];
            s_val[t] = g_vals[j];
        }
        __syncthreads();
        int cnt = min(256, end - cb);
        for (int u = 0; u < cnt; ++u) {
            float a = s_val[u];
            float4 v = *(const float4*)(Tsrc + (size_t)s_col[u] * FTOT + c0);
            acc.x += a * v.x;
            acc.y += a * v.y;
            acc.z += a * v.z;
            acc.w += a * v.w;
        }
        __syncthreads();
    }

    if (p2I >= 0) {
        float4 p = *(const float4*)(g_buf[p2I] + (size_t)m * FTOT + c0);
        acc.x = 2.f * acc.x - p.x;
        acc.y = 2.f * acc.y - p.y;
        acc.z = 2.f * acc.z - p.z;
        acc.w = 2.f * acc.w - p.w;
    }

    *(float4*)(Tdst + (size_t)m * FTOT + c0) = acc;
    stage_row(s_x, c0, acc);
    __syncthreads();
    gemm_epilogue(s_x, s_w, m, t, nullptr, out, /*init=*/false);
}

// ---------------- launch ----------------
extern "C" void kernel_launch(void* const* d_in, const int* in_sizes, int n_in,
                              void* d_out, int out_size) {
    const float* x      = (const float*)d_in[0];  // [16, 20000, 64]
    const float* L_vals = (const float*)d_in[1];  // [160000]
    const float* weight = (const float*)d_in[2];  // [384, 64]
    const float* bias   = (const float*)d_in[3];  // [64]
    const int*   L_rows = (const int*)d_in[4];    // [160000]
    const int*   L_cols = (const int*)d_in[5];    // [160000]
    float*       out    = (float*)d_out;          // [16, 20000, 64]

    (void)in_sizes; (void)n_in; (void)out_size;

    // CSR build (fresh every call -> deterministic work, graph-capturable)
    zero_cnt_kernel<<<(MM + 255) / 256, 256>>>();
    count_kernel<<<(NNZC + 255) / 256, 256>>>(L_rows);
    scan_kernel<<<1, 1024>>>();
    scatter_kernel<<<(NNZC + 255) / 256, 256>>>(L_rows, L_cols, L_vals);

    // k = 0: T0 = x0, out = bias + T0 @ W0
    x0_kernel<<<MM, 256>>>(x, weight, bias, out);

    // k = 1: T1 = L @ T0
    term_kernel<<<MM, 256>>>(0, 1, -1, 1, weight, out);
    // k = 2..5: Tk = 2 L T_{k-1} - T_{k-2}, buffers rotate
    term_kernel<<<MM, 256>>>(1, 2, 0, 2, weight, out);
    term_kernel<<<MM, 256>>>(2, 0, 1, 3, weight, out);
    term_kernel<<<MM, 256>>>(0, 1, 2, 4, weight, out);
    term_kernel<<<MM, 256>>>(1, 2, 0, 5, weight, out);
}

// round 2
// speedup vs baseline: 2.3047x; 2.3047x over previous
#include <cuda_runtime.h>
#include <cstdint>

#define MM    20000
#define NN    16
#define FINC  64
#define FOUTC 64
#define KK    6
#define NNZC  160000
#define FTOT  1024

// ---------------- device scratch ----------------
__device__ int   g_cnt[MM];
__device__ int   g_rowptr[MM + 1];
__device__ int   g_cursor[MM];
__device__ int   g_cols[NNZC];
__device__ float g_vals[NNZC];
// 6 Chebyshev term buffers [M, FTOT] fp32 (80 MB each)
__device__ __align__(16) float g_buf[KK][(size_t)MM * FTOT];
// W pre-arranged into mma B-fragment order, tf32 bits:
// [k][fin_chunk][fo_tile][lane][2]  = 6*8*8*32*2 = 24576 words
__device__ uint32_t g_Wfrag[24576];

// ---------------- helpers ----------------
__device__ __forceinline__ uint32_t f2tf32(float f) {
    uint32_t r;
    asm("cvt.rna.tf32.f32 %0, %1;" : "=r"(r) : "f"(f));
    return r;
}

__device__ __forceinline__ void mma_tf32(float c[4],
                                         uint32_t a0, uint32_t a1, uint32_t a2, uint32_t a3,
                                         uint32_t b0, uint32_t b1) {
    asm volatile(
        "mma.sync.aligned.m16n8k8.row.col.f32.tf32.tf32.f32 "
        "{%0,%1,%2,%3}, {%4,%5,%6,%7}, {%8,%9}, {%0,%1,%2,%3};"
        : "+f"(c[0]), "+f"(c[1]), "+f"(c[2]), "+f"(c[3])
        : "r"(a0), "r"(a1), "r"(a2), "r"(a3), "r"(b0), "r"(b1));
}

// ---------------- CSR build ----------------
__global__ void zero_cnt_kernel() {
    int i = blockIdx.x * blockDim.x + threadIdx.x;
    if (i < MM) g_cnt[i] = 0;
}

__global__ void count_kernel(const int* __restrict__ rows) {
    int i = blockIdx.x * blockDim.x + threadIdx.x;
    if (i < NNZC) atomicAdd(&g_cnt[rows[i]], 1);
}

__global__ void scan_kernel() {
    __shared__ int s[1024];
    int t = threadIdx.x;
    int carry = 0;
    for (int base = 0; base < MM; base += 1024) {
        int idx = base + t;
        int v = (idx < MM) ? g_cnt[idx] : 0;
        s[t] = v;
        __syncthreads();
        #pragma unroll
        for (int off = 1; off < 1024; off <<= 1) {
            int tmp = (t >= off) ? s[t - off] : 0;
            __syncthreads();
            s[t] += tmp;
            __syncthreads();
        }
        int inc = s[t];
        int excl = carry + inc - v;
        if (idx < MM) {
            g_rowptr[idx] = excl;
            g_cursor[idx] = excl;
        }
        carry += s[1023];
        __syncthreads();
    }
    if (t == 0) g_rowptr[MM] = carry;
}

__global__ void scatter_kernel(const int* __restrict__ rows,
                               const int* __restrict__ cols,
                               const float* __restrict__ vals) {
    int i = blockIdx.x * blockDim.x + threadIdx.x;
    if (i < NNZC) {
        int r = rows[i];
        int p = atomicAdd(&g_cursor[r], 1);
        g_cols[p] = cols[i];
        g_vals[p] = vals[i];
    }
}

// ---------------- W fragment prep (tf32) ----------------
// b0: (row=fin_local=lane&3, col=fo=lane>>2), b1: row+4
__global__ void prep_w_kernel(const float* __restrict__ W) {
    int tid = blockIdx.x * blockDim.x + threadIdx.x;   // 12288 threads
    int lane = tid & 31;
    int tile = tid >> 5;          // 0..383
    if (tile >= 384) return;
    int k  = tile >> 6;           // /64
    int fc = (tile >> 3) & 7;
    int ft = tile & 7;
    int la = lane & 3;
    int g  = lane >> 2;
    int fo  = ft * 8 + g;
    int fin0 = fc * 8 + la;
    uint32_t b0 = f2tf32(W[(fin0 * KK + k) * FOUTC + fo]);
    uint32_t b1 = f2tf32(W[((fin0 + 4) * KK + k) * FOUTC + fo]);
    g_Wfrag[tile * 64 + lane * 2 + 0] = b0;
    g_Wfrag[tile * 64 + lane * 2 + 1] = b1;
}

// ---------------- k = 0: build T0 from x ----------------
__global__ void __launch_bounds__(256) x0_kernel(const float* __restrict__ x) {
    int m = blockIdx.x;
    int t = threadIdx.x;
    int c0  = t * 4;
    int fin = c0 >> 4;
    float v0 = x[((size_t)((c0 + 0) & 15) * MM + m) * FINC + fin];
    float v1 = x[((size_t)((c0 + 1) & 15) * MM + m) * FINC + fin];
    float v2 = x[((size_t)((c0 + 2) & 15) * MM + m) * FINC + fin];
    float v3 = x[((size_t)((c0 + 3) & 15) * MM + m) * FINC + fin];
    *(float4*)(g_buf[0] + (size_t)m * FTOT + c0) = make_float4(v0, v1, v2, v3);
}

// ---------------- SpMM + recurrence ----------------
__global__ void __launch_bounds__(256) term_kernel(int srcI, int dstI, int p2I) {
    __shared__ int   s_col[256];
    __shared__ float s_val[256];
    int m = blockIdx.x;
    int t = threadIdx.x;

    const float* Tsrc = g_buf[srcI];
    float*       Tdst = g_buf[dstI];

    int start = g_rowptr[m];
    int end   = g_rowptr[m + 1];

    float4 acc = make_float4(0.f, 0.f, 0.f, 0.f);
    int c0 = t * 4;

    for (int cb = start; cb < end; cb += 256) {
        int j = cb + t;
        if (j < end) {
            s_col[t] = g_cols[j];
            s_val[t] = g_vals[j];
        }
        __syncthreads();
        int cnt = min(256, end - cb);
        for (int u = 0; u < cnt; ++u) {
            float a = s_val[u];
            float4 v = *(const float4*)(Tsrc + (size_t)s_col[u] * FTOT + c0);
            acc.x += a * v.x;
            acc.y += a * v.y;
            acc.z += a * v.z;
            acc.w += a * v.w;
        }
        __syncthreads();
    }

    if (p2I >= 0) {
        float4 p = *(const float4*)(g_buf[p2I] + (size_t)m * FTOT + c0);
        acc.x = 2.f * acc.x - p.x;
        acc.y = 2.f * acc.y - p.y;
        acc.z = 2.f * acc.z - p.z;
        acc.w = 2.f * acc.w - p.w;
    }

    *(float4*)(Tdst + (size_t)m * FTOT + c0) = acc;
}

// ---------------- tensor-core GEMM ----------------
// out[n,m,fo] = bias[fo] + sum_k sum_fin T_k[m, fin*16+n] * W[(fin*6+k)*64+fo]
// One warp handles one m at a time: 16x384 @ 384x64 via m16n8k8 tf32 mma.
#define GWARPS 16
__global__ void __launch_bounds__(GWARPS * 32, 1)
gemm_kernel(const float* __restrict__ bias, float* __restrict__ out) {
    extern __shared__ uint32_t smem[];
    uint32_t* s_W = smem;                          // 24576 words (96KB)
    int tid  = threadIdx.x;
    int w    = tid >> 5;
    int lane = tid & 31;
    uint32_t* s_A = smem + 24576 + w * FTOT;       // 1024 words per warp

    // load W fragments once per block
    for (int i = tid; i < 24576; i += GWARPS * 32) s_W[i] = g_Wfrag[i];
    __syncthreads();

    int g  = lane >> 2;
    int la = lane & 3;

    // bias for this thread's output columns (same for rows g and g+8)
    float2 bv[8];
    #pragma unroll
    for (int ft = 0; ft < 8; ++ft) {
        bv[ft].x = bias[ft * 8 + la * 2 + 0];
        bv[ft].y = bias[ft * 8 + la * 2 + 1];
    }

    int gw = blockIdx.x * GWARPS + w;
    const int NWARP = gridDim.x * GWARPS;

    // preload term 0 of first m
    float4 pf[8];
    {
        int m0 = gw;
        if (m0 < MM) {
            const float4* src = (const float4*)(g_buf[0] + (size_t)m0 * FTOT);
            #pragma unroll
            for (int j = 0; j < 8; ++j) pf[j] = src[j * 32 + lane];
        }
    }

    for (int m = gw; m < MM; m += NWARP) {
        float c[8][4];
        #pragma unroll
        for (int ft = 0; ft < 8; ++ft)
            c[ft][0] = c[ft][1] = c[ft][2] = c[ft][3] = 0.f;

        #pragma unroll
        for (int k = 0; k < KK; ++k) {
            // store staged term (tf32-converted) to this warp's smem slab
            #pragma unroll
            for (int j = 0; j < 8; ++j) {
                uint4 tv;
                tv.x = f2tf32(pf[j].x);
                tv.y = f2tf32(pf[j].y);
                tv.z = f2tf32(pf[j].z);
                tv.w = f2tf32(pf[j].w);
                *(uint4*)(s_A + j * 128 + lane * 4) = tv;
            }
            __syncwarp();

            // prefetch next term (or next m's term 0) during compute
            if (k < KK - 1) {
                const float4* src = (const float4*)(g_buf[k + 1] + (size_t)m * FTOT);
                #pragma unroll
                for (int j = 0; j < 8; ++j) pf[j] = src[j * 32 + lane];
            } else {
                int mn = m + NWARP;
                if (mn < MM) {
                    const float4* src = (const float4*)(g_buf[0] + (size_t)mn * FTOT);
                    #pragma unroll
                    for (int j = 0; j < 8; ++j) pf[j] = src[j * 32 + lane];
                }
            }

            #pragma unroll
            for (int fc = 0; fc < 8; ++fc) {
                int base = (fc * 8 + la) * 16 + g;
                uint32_t a0 = s_A[base];
                uint32_t a1 = s_A[base + 8];
                uint32_t a2 = s_A[base + 64];
                uint32_t a3 = s_A[base + 72];
                const uint32_t* wb = s_W + ((k * 8 + fc) * 8) * 64 + lane * 2;
                #pragma unroll
                for (int ft = 0; ft < 8; ++ft) {
                    uint2 b = *(const uint2*)(wb + ft * 64);
                    mma_tf32(c[ft], a0, a1, a2, a3, b.x, b.y);
                }
            }
            __syncwarp();
        }

        // epilogue: rows n=g and n=g+8, cols fo = ft*8 + la*2 (+1)
        float* o0 = out + ((size_t)g * MM + m) * 64 + la * 2;
        float* o1 = out + ((size_t)(g + 8) * MM + m) * 64 + la * 2;
        #pragma unroll
        for (int ft = 0; ft < 8; ++ft) {
            float2 v0, v1;
            v0.x = c[ft][0] + bv[ft].x;
            v0.y = c[ft][1] + bv[ft].y;
            v1.x = c[ft][2] + bv[ft].x;
            v1.y = c[ft][3] + bv[ft].y;
            *(float2*)(o0 + ft * 8) = v0;
            *(float2*)(o1 + ft * 8) = v1;
        }
    }
}

// ---------------- launch ----------------
extern "C" void kernel_launch(void* const* d_in, const int* in_sizes, int n_in,
                              void* d_out, int out_size) {
    const float* x      = (const float*)d_in[0];
    const float* L_vals = (const float*)d_in[1];
    const float* weight = (const float*)d_in[2];
    const float* bias   = (const float*)d_in[3];
    const int*   L_rows = (const int*)d_in[4];
    const int*   L_cols = (const int*)d_in[5];
    float*       out    = (float*)d_out;

    (void)in_sizes; (void)n_in; (void)out_size;

    // CSR build
    zero_cnt_kernel<<<(MM + 255) / 256, 256>>>();
    count_kernel<<<(NNZC + 255) / 256, 256>>>(L_rows);
    scan_kernel<<<1, 1024>>>();
    scatter_kernel<<<(NNZC + 255) / 256, 256>>>(L_rows, L_cols, L_vals);

    // W fragments
    prep_w_kernel<<<48, 256>>>(weight);

    // T0
    x0_kernel<<<MM, 256>>>(x);
    // T1..T5
    term_kernel<<<MM, 256>>>(0, 1, -1);
    term_kernel<<<MM, 256>>>(1, 2, 0);
    term_kernel<<<MM, 256>>>(2, 3, 1);
    term_kernel<<<MM, 256>>>(3, 4, 2);
    term_kernel<<<MM, 256>>>(4, 5, 3);

    // GEMM (160KB dynamic smem)
    cudaFuncSetAttribute(gemm_kernel, cudaFuncAttributeMaxDynamicSharedMemorySize,
                         (24576 + GWARPS * FTOT) * 4);
    gemm_kernel<<<148, GWARPS * 32, (24576 + GWARPS * FTOT) * 4>>>(bias, out);
}

// round 3
// speedup vs baseline: 4.0983x; 1.7783x over previous
#include <cuda_runtime.h>
#include <cuda_fp16.h>
#include <cstdint>

#define MM    20000
#define NN    16
#define FINC  64
#define FOUTC 64
#define KK    6
#define NNZC  160000
#define FTOT  1024

// ---------------- device scratch ----------------
__device__ int   g_cnt[MM];
__device__ int   g_rowptr[MM + 1];
__device__ int   g_cursor[MM];
__device__ int   g_cols[NNZC];
__device__ float g_vals[NNZC];
// 6 Chebyshev term buffers [M, FTOT] fp16 (40 MB each)
__device__ __align__(16) __half g_buf16[KK][(size_t)MM * FTOT];
// W in mma B-fragment order (tf32 bits): [k][fc][ft][lane][2] = 24576 words
__device__ uint32_t g_Wfrag[24576];

// ---------------- helpers ----------------
__device__ __forceinline__ uint32_t f2tf32(float f) {
    uint32_t r;
    asm("cvt.rna.tf32.f32 %0, %1;" : "=r"(r) : "f"(f));
    return r;
}

__device__ __forceinline__ void mma_tf32(float c[4],
                                         uint32_t a0, uint32_t a1, uint32_t a2, uint32_t a3,
                                         uint32_t b0, uint32_t b1) {
    asm volatile(
        "mma.sync.aligned.m16n8k8.row.col.f32.tf32.tf32.f32 "
        "{%0,%1,%2,%3}, {%4,%5,%6,%7}, {%8,%9}, {%0,%1,%2,%3};"
        : "+f"(c[0]), "+f"(c[1]), "+f"(c[2]), "+f"(c[3])
        : "r"(a0), "r"(a1), "r"(a2), "r"(a3), "r"(b0), "r"(b1));
}

// ---------------- CSR build ----------------
__global__ void zero_cnt_kernel() {
    int i = blockIdx.x * blockDim.x + threadIdx.x;
    if (i < MM) g_cnt[i] = 0;
}

__global__ void count_kernel(const int* __restrict__ rows) {
    int i = blockIdx.x * blockDim.x + threadIdx.x;
    if (i < NNZC) atomicAdd(&g_cnt[rows[i]], 1);
}

__global__ void scan_kernel() {
    __shared__ int s[1024];
    int t = threadIdx.x;
    int carry = 0;
    for (int base = 0; base < MM; base += 1024) {
        int idx = base + t;
        int v = (idx < MM) ? g_cnt[idx] : 0;
        s[t] = v;
        __syncthreads();
        #pragma unroll
        for (int off = 1; off < 1024; off <<= 1) {
            int tmp = (t >= off) ? s[t - off] : 0;
            __syncthreads();
            s[t] += tmp;
            __syncthreads();
        }
        int inc = s[t];
        int excl = carry + inc - v;
        if (idx < MM) {
            g_rowptr[idx] = excl;
            g_cursor[idx] = excl;
        }
        carry += s[1023];
        __syncthreads();
    }
    if (t == 0) g_rowptr[MM] = carry;
}

__global__ void scatter_kernel(const int* __restrict__ rows,
                               const int* __restrict__ cols,
                               const float* __restrict__ vals) {
    int i = blockIdx.x * blockDim.x + threadIdx.x;
    if (i < NNZC) {
        int r = rows[i];
        int p = atomicAdd(&g_cursor[r], 1);
        g_cols[p] = cols[i];
        g_vals[p] = vals[i];
    }
}

// ---------------- W fragment prep (tf32, full fp32 source precision) ----------------
__global__ void prep_w_kernel(const float* __restrict__ W) {
    int tid = blockIdx.x * blockDim.x + threadIdx.x;
    int lane = tid & 31;
    int tile = tid >> 5;          // 0..383
    if (tile >= 384) return;
    int k  = tile >> 6;
    int fc = (tile >> 3) & 7;
    int ft = tile & 7;
    int la = lane & 3;
    int g  = lane >> 2;
    int fo   = ft * 8 + g;
    int fin0 = fc * 8 + la;
    g_Wfrag[tile * 64 + lane * 2 + 0] = f2tf32(W[(fin0 * KK + k) * FOUTC + fo]);
    g_Wfrag[tile * 64 + lane * 2 + 1] = f2tf32(W[((fin0 + 4) * KK + k) * FOUTC + fo]);
}

// ---------------- k = 0: build T0 (fp16) from x ----------------
__global__ void __launch_bounds__(128) x0_kernel(const float* __restrict__ x) {
    int m = blockIdx.x;
    int t = threadIdx.x;
    int c0  = t * 8;
    int fin = c0 >> 4;
    int n0  = c0 & 15;           // 0 or 8
    __half h[8];
    #pragma unroll
    for (int i = 0; i < 8; ++i) {
        float v = x[((size_t)(n0 + i) * MM + m) * FINC + fin];
        h[i] = __float2half_rn(v);
    }
    *(uint4*)(g_buf16[0] + (size_t)m * FTOT + c0) = *(uint4*)h;
}

// ---------------- SpMM + recurrence (fp16 storage, fp32 accumulate) ----------------
__global__ void __launch_bounds__(128) term_kernel(int srcI, int dstI, int p2I) {
    __shared__ int   s_col[128];
    __shared__ float s_val[128];
    int m = blockIdx.x;
    int t = threadIdx.x;

    const uint4* Tsrc = (const uint4*)g_buf16[srcI];   // 128 uint4 per row

    int start = g_rowptr[m];
    int end   = g_rowptr[m + 1];

    float acc[8];
    #pragma unroll
    for (int i = 0; i < 8; ++i) acc[i] = 0.f;

    for (int cb = start; cb < end; cb += 128) {
        int j = cb + t;
        if (j < end) {
            s_col[t] = g_cols[j];
            s_val[t] = g_vals[j];
        }
        __syncthreads();
        int cnt = min(128, end - cb);
        #pragma unroll 2
        for (int u = 0; u < cnt; ++u) {
            float a = s_val[u];
            uint4 v = Tsrc[(size_t)s_col[u] * 128 + t];
            const half2* hp = (const half2*)&v;
            #pragma unroll
            for (int i = 0; i < 4; ++i) {
                float2 f = __half22float2(hp[i]);
                acc[2 * i]     += a * f.x;
                acc[2 * i + 1] += a * f.y;
            }
        }
        __syncthreads();
    }

    if (p2I >= 0) {
        uint4 p = ((const uint4*)g_buf16[p2I])[(size_t)m * 128 + t];
        const half2* pp = (const half2*)&p;
        #pragma unroll
        for (int i = 0; i < 4; ++i) {
            float2 f = __half22float2(pp[i]);
            acc[2 * i]     = 2.f * acc[2 * i]     - f.x;
            acc[2 * i + 1] = 2.f * acc[2 * i + 1] - f.y;
        }
    }

    uint4 o;
    half2* op = (half2*)&o;
    #pragma unroll
    for (int i = 0; i < 4; ++i)
        op[i] = __floats2half2_rn(acc[2 * i], acc[2 * i + 1]);
    ((uint4*)g_buf16[dstI])[(size_t)m * 128 + t] = o;
}

// ---------------- tensor-core GEMM (fp16 terms -> tf32 mma) ----------------
// out[n,m,fo] = bias[fo] + sum_k sum_fin T_k[m, fin*16+n] * W[(fin*6+k)*64+fo]
#define GWARPS 16
__global__ void __launch_bounds__(GWARPS * 32, 1)
gemm_kernel(const float* __restrict__ bias, float* __restrict__ out) {
    extern __shared__ uint32_t smem[];
    uint32_t* s_W = smem;                          // 24576 words (96KB)
    int tid  = threadIdx.x;
    int w    = tid >> 5;
    int lane = tid & 31;
    uint32_t* s_A = smem + 24576 + w * FTOT;       // 1024 words / warp

    for (int i = tid; i < 24576; i += GWARPS * 32) s_W[i] = g_Wfrag[i];
    __syncthreads();

    int g  = lane >> 2;
    int la = lane & 3;

    float2 bv[8];
    #pragma unroll
    for (int ft = 0; ft < 8; ++ft) {
        bv[ft].x = bias[ft * 8 + la * 2 + 0];
        bv[ft].y = bias[ft * 8 + la * 2 + 1];
    }

    int gw = blockIdx.x * GWARPS + w;
    const int NWARP = gridDim.x * GWARPS;

    // preload term 0 of first m (fp16 row: 128 uint4; lane takes j*32+lane)
    uint4 pf[4];
    {
        int m0 = gw;
        if (m0 < MM) {
            const uint4* src = (const uint4*)(g_buf16[0] + (size_t)m0 * FTOT);
            #pragma unroll
            for (int j = 0; j < 4; ++j) pf[j] = src[j * 32 + lane];
        }
    }

    for (int m = gw; m < MM; m += NWARP) {
        float c[8][4];
        #pragma unroll
        for (int ft = 0; ft < 8; ++ft)
            c[ft][0] = c[ft][1] = c[ft][2] = c[ft][3] = 0.f;

        #pragma unroll
        for (int k = 0; k < KK; ++k) {
            // stage: fp16 -> fp32 bits (exact; valid tf32 input) into smem
            #pragma unroll
            for (int j = 0; j < 4; ++j) {
                const half2* hp = (const half2*)&pf[j];
                float f[8];
                #pragma unroll
                for (int i = 0; i < 4; ++i) {
                    float2 t2 = __half22float2(hp[i]);
                    f[2 * i] = t2.x; f[2 * i + 1] = t2.y;
                }
                float* dst = (float*)(s_A + (j * 32 + lane) * 8);
                ((float4*)dst)[0] = make_float4(f[0], f[1], f[2], f[3]);
                ((float4*)dst)[1] = make_float4(f[4], f[5], f[6], f[7]);
            }
            __syncwarp();

            // prefetch next term (or next m's term 0)
            if (k < KK - 1) {
                const uint4* src = (const uint4*)(g_buf16[k + 1] + (size_t)m * FTOT);
                #pragma unroll
                for (int j = 0; j < 4; ++j) pf[j] = src[j * 32 + lane];
            } else {
                int mn = m + NWARP;
                if (mn < MM) {
                    const uint4* src = (const uint4*)(g_buf16[0] + (size_t)mn * FTOT);
                    #pragma unroll
                    for (int j = 0; j < 4; ++j) pf[j] = src[j * 32 + lane];
                }
            }

            #pragma unroll
            for (int fc = 0; fc < 8; ++fc) {
                int base = (fc * 8 + la) * 16 + g;
                uint32_t a0 = s_A[base];
                uint32_t a1 = s_A[base + 8];
                uint32_t a2 = s_A[base + 64];
                uint32_t a3 = s_A[base + 72];
                const uint32_t* wb = s_W + ((k * 8 + fc) * 8) * 64 + lane * 2;
                #pragma unroll
                for (int ft = 0; ft < 8; ++ft) {
                    uint2 b = *(const uint2*)(wb + ft * 64);
                    mma_tf32(c[ft], a0, a1, a2, a3, b.x, b.y);
                }
            }
            __syncwarp();
        }

        float* o0 = out + ((size_t)g * MM + m) * 64 + la * 2;
        float* o1 = out + ((size_t)(g + 8) * MM + m) * 64 + la * 2;
        #pragma unroll
        for (int ft = 0; ft < 8; ++ft) {
            float2 v0, v1;
            v0.x = c[ft][0] + bv[ft].x;
            v0.y = c[ft][1] + bv[ft].y;
            v1.x = c[ft][2] + bv[ft].x;
            v1.y = c[ft][3] + bv[ft].y;
            *(float2*)(o0 + ft * 8) = v0;
            *(float2*)(o1 + ft * 8) = v1;
        }
    }
}

// ---------------- launch ----------------
extern "C" void kernel_launch(void* const* d_in, const int* in_sizes, int n_in,
                              void* d_out, int out_size) {
    const float* x      = (const float*)d_in[0];
    const float* L_vals = (const float*)d_in[1];
    const float* weight = (const float*)d_in[2];
    const float* bias   = (const float*)d_in[3];
    const int*   L_rows = (const int*)d_in[4];
    const int*   L_cols = (const int*)d_in[5];
    float*       out    = (float*)d_out;

    (void)in_sizes; (void)n_in; (void)out_size;

    zero_cnt_kernel<<<(MM + 255) / 256, 256>>>();
    count_kernel<<<(NNZC + 255) / 256, 256>>>(L_rows);
    scan_kernel<<<1, 1024>>>();
    scatter_kernel<<<(NNZC + 255) / 256, 256>>>(L_rows, L_cols, L_vals);

    prep_w_kernel<<<48, 256>>>(weight);

    x0_kernel<<<MM, 128>>>(x);
    term_kernel<<<MM, 128>>>(0, 1, -1);
    term_kernel<<<MM, 128>>>(1, 2, 0);
    term_kernel<<<MM, 128>>>(2, 3, 1);
    term_kernel<<<MM, 128>>>(3, 4, 2);
    term_kernel<<<MM, 128>>>(4, 5, 3);

    cudaFuncSetAttribute(gemm_kernel, cudaFuncAttributeMaxDynamicSharedMemorySize,
                         (24576 + GWARPS * FTOT) * 4);
    gemm_kernel<<<148, GWARPS * 32, (24576 + GWARPS * FTOT) * 4>>>(bias, out);
}

// round 4
// speedup vs baseline: 4.7057x; 1.1482x over previous
#include <cuda_runtime.h>
#include <cuda_fp16.h>
#include <cstdint>

#define MM    20000
#define NN    16
#define FINC  64
#define FOUTC 64
#define KK    6
#define NNZC  160000
#define FTOT  1024

// ---------------- device scratch ----------------
__device__ int   g_cnt[MM];
__device__ int   g_rowptr[MM + 1];
__device__ int   g_cursor[MM];
__device__ int   g_cols[NNZC];
__device__ float g_vals[NNZC];
// 6 Chebyshev term buffers [M, FTOT] fp16, layout c = n*64 + fin (fin fastest)
__device__ __align__(16) __half g_buf16[KK][(size_t)MM * FTOT];
// W as fp16 mma B-fragments: [k][fc(4)][ft(8)][lane(32)][2] uint32(half2) = 12288 words (48KB)
__device__ uint32_t g_WfragH[12288];

// ---------------- helpers ----------------
__device__ __forceinline__ void mma_f16(float c[4],
                                        uint32_t a0, uint32_t a1, uint32_t a2, uint32_t a3,
                                        uint32_t b0, uint32_t b1) {
    asm volatile(
        "mma.sync.aligned.m16n8k16.row.col.f32.f16.f16.f32 "
        "{%0,%1,%2,%3}, {%4,%5,%6,%7}, {%8,%9}, {%0,%1,%2,%3};"
        : "+f"(c[0]), "+f"(c[1]), "+f"(c[2]), "+f"(c[3])
        : "r"(a0), "r"(a1), "r"(a2), "r"(a3), "r"(b0), "r"(b1));
}

__device__ __forceinline__ void ldsm_x4(uint32_t& a0, uint32_t& a1,
                                        uint32_t& a2, uint32_t& a3, uint32_t saddr) {
    asm volatile("ldmatrix.sync.aligned.m8n8.x4.shared.b16 {%0,%1,%2,%3}, [%4];"
                 : "=r"(a0), "=r"(a1), "=r"(a2), "=r"(a3) : "r"(saddr));
}

// ---------------- CSR build ----------------
__global__ void zero_cnt_kernel() {
    int i = blockIdx.x * blockDim.x + threadIdx.x;
    if (i < MM) g_cnt[i] = 0;
}

__global__ void count_kernel(const int* __restrict__ rows) {
    int i = blockIdx.x * blockDim.x + threadIdx.x;
    if (i < NNZC) atomicAdd(&g_cnt[rows[i]], 1);
}

__global__ void scan_kernel() {
    __shared__ int s[1024];
    int t = threadIdx.x;
    int carry = 0;
    for (int base = 0; base < MM; base += 1024) {
        int idx = base + t;
        int v = (idx < MM) ? g_cnt[idx] : 0;
        s[t] = v;
        __syncthreads();
        #pragma unroll
        for (int off = 1; off < 1024; off <<= 1) {
            int tmp = (t >= off) ? s[t - off] : 0;
            __syncthreads();
            s[t] += tmp;
            __syncthreads();
        }
        int inc = s[t];
        int excl = carry + inc - v;
        if (idx < MM) {
            g_rowptr[idx] = excl;
            g_cursor[idx] = excl;
        }
        carry += s[1023];
        __syncthreads();
    }
    if (t == 0) g_rowptr[MM] = carry;
}

__global__ void scatter_kernel(const int* __restrict__ rows,
                               const int* __restrict__ cols,
                               const float* __restrict__ vals) {
    int i = blockIdx.x * blockDim.x + threadIdx.x;
    if (i < NNZC) {
        int r = rows[i];
        int p = atomicAdd(&g_cursor[r], 1);
        g_cols[p] = cols[i];
        g_vals[p] = vals[i];
    }
}

// ---------------- W fragment prep (fp16) ----------------
// B fragment m16n8k16: b0 = (k-rows la*2, la*2+1; col fo=ft*8+g), b1 = rows +8
// k-rows map to fin = fc*16 + row. W index: weight[(fin*KK + k)*FOUTC + fo].
__global__ void prep_w_kernel(const float* __restrict__ W) {
    int tid  = blockIdx.x * blockDim.x + threadIdx.x;    // 6144 threads
    int lane = tid & 31;
    int tile = tid >> 5;            // 0..191 = k*32 + fc*8 + ft
    if (tile >= 192) return;
    int k  = tile >> 5;
    int fc = (tile >> 3) & 3;
    int ft = tile & 7;
    int la = lane & 3;
    int g  = lane >> 2;
    int fo = ft * 8 + g;
    int f0 = fc * 16 + la * 2;
    __half2 b0 = __floats2half2_rn(W[((f0 + 0) * KK + k) * FOUTC + fo],
                                   W[((f0 + 1) * KK + k) * FOUTC + fo]);
    __half2 b1 = __floats2half2_rn(W[((f0 + 8) * KK + k) * FOUTC + fo],
                                   W[((f0 + 9) * KK + k) * FOUTC + fo]);
    g_WfragH[tile * 64 + lane * 2 + 0] = *(uint32_t*)&b0;
    g_WfragH[tile * 64 + lane * 2 + 1] = *(uint32_t*)&b1;
}

// ---------------- k = 0: build T0 (fp16, [n][fin] layout) from x ----------------
__global__ void __launch_bounds__(128) x0_kernel(const float* __restrict__ x) {
    int m = blockIdx.x;
    int t = threadIdx.x;
    int n    = t >> 3;
    int fin0 = (t & 7) * 8;
    const float4* xp = (const float4*)(x + ((size_t)n * MM + m) * FINC + fin0);
    float4 v0 = xp[0];
    float4 v1 = xp[1];
    __half h[8];
    h[0] = __float2half_rn(v0.x); h[1] = __float2half_rn(v0.y);
    h[2] = __float2half_rn(v0.z); h[3] = __float2half_rn(v0.w);
    h[4] = __float2half_rn(v1.x); h[5] = __float2half_rn(v1.y);
    h[6] = __float2half_rn(v1.z); h[7] = __float2half_rn(v1.w);
    *(uint4*)(g_buf16[0] + (size_t)m * FTOT + t * 8) = *(uint4*)h;
}

// ---------------- SpMM + recurrence (fp16 storage, fp32 accumulate) ----------------
__global__ void __launch_bounds__(128) term_kernel(int srcI, int dstI, int p2I) {
    int m = blockIdx.x;
    int t = threadIdx.x;

    const uint4* Tsrc = (const uint4*)g_buf16[srcI];

    int start = g_rowptr[m];
    int end   = g_rowptr[m + 1];

    float acc[8];
    #pragma unroll
    for (int i = 0; i < 8; ++i) acc[i] = 0.f;

    int j = start;
    for (; j + 3 < end; j += 4) {
        float a0 = g_vals[j],     a1 = g_vals[j + 1];
        float a2 = g_vals[j + 2], a3 = g_vals[j + 3];
        int   c0 = g_cols[j],     c1 = g_cols[j + 1];
        int   c2 = g_cols[j + 2], c3 = g_cols[j + 3];
        uint4 v0 = Tsrc[(size_t)c0 * 128 + t];
        uint4 v1 = Tsrc[(size_t)c1 * 128 + t];
        uint4 v2 = Tsrc[(size_t)c2 * 128 + t];
        uint4 v3 = Tsrc[(size_t)c3 * 128 + t];
        const half2* h0 = (const half2*)&v0;
        const half2* h1 = (const half2*)&v1;
        const half2* h2 = (const half2*)&v2;
        const half2* h3 = (const half2*)&v3;
        #pragma unroll
        for (int i = 0; i < 4; ++i) {
            float2 f0 = __half22float2(h0[i]);
            float2 f1 = __half22float2(h1[i]);
            float2 f2 = __half22float2(h2[i]);
            float2 f3 = __half22float2(h3[i]);
            acc[2*i]   += a0 * f0.x + a1 * f1.x + a2 * f2.x + a3 * f3.x;
            acc[2*i+1] += a0 * f0.y + a1 * f1.y + a2 * f2.y + a3 * f3.y;
        }
    }
    for (; j < end; ++j) {
        float a = g_vals[j];
        int   c = g_cols[j];
        uint4 v = Tsrc[(size_t)c * 128 + t];
        const half2* hp = (const half2*)&v;
        #pragma unroll
        for (int i = 0; i < 4; ++i) {
            float2 f = __half22float2(hp[i]);
            acc[2*i]   += a * f.x;
            acc[2*i+1] += a * f.y;
        }
    }

    if (p2I >= 0) {
        uint4 p = ((const uint4*)g_buf16[p2I])[(size_t)m * 128 + t];
        const half2* pp = (const half2*)&p;
        #pragma unroll
        for (int i = 0; i < 4; ++i) {
            float2 f = __half22float2(pp[i]);
            acc[2*i]   = 2.f * acc[2*i]   - f.x;
            acc[2*i+1] = 2.f * acc[2*i+1] - f.y;
        }
    }

    uint4 o;
    half2* op = (half2*)&o;
    #pragma unroll
    for (int i = 0; i < 4; ++i)
        op[i] = __floats2half2_rn(acc[2*i], acc[2*i+1]);
    ((uint4*)g_buf16[dstI])[(size_t)m * 128 + t] = o;
}

// ---------------- tensor-core GEMM (fp16 HMMA) ----------------
// out[n,m,fo] = bias[fo] + sum_k sum_fin T_k[m, n*64+fin] * W[(fin*6+k)*64+fo]
#define GWARPS 16
#define A_STRIDE 72                       // halves per staged row (144B, LDSM conflict-free)
#define SMEM_W_WORDS 12288                // 48KB
#define SMEM_A_BYTES (16 * A_STRIDE * 2)  // 2304B per warp
#define SMEM_TOTAL (SMEM_W_WORDS * 4 + GWARPS * SMEM_A_BYTES)

__global__ void __launch_bounds__(GWARPS * 32, 2)
gemm_kernel(const float* __restrict__ bias, float* __restrict__ out) {
    extern __shared__ uint32_t smem[];
    uint32_t* s_W = smem;
    int tid  = threadIdx.x;
    int w    = tid >> 5;
    int lane = tid & 31;
    __half* s_A = (__half*)((char*)smem + SMEM_W_WORDS * 4 + w * SMEM_A_BYTES);

    for (int i = tid; i < SMEM_W_WORDS; i += GWARPS * 32) s_W[i] = g_WfragH[i];
    __syncthreads();

    int g  = lane >> 2;
    int la = lane & 3;

    // ldmatrix source address for this lane (row = lane&15, col-half = (lane>>4)*8)
    uint32_t a_base = (uint32_t)__cvta_generic_to_shared(s_A)
                    + ((lane & 15) * A_STRIDE + ((lane >> 4) * 8)) * 2;
    // staging: lane stores uint4 j: c0=(j*32+lane)*8 -> n=(j*32+lane)>>3, fin0=((j*32+lane)&7)*8
    __half* st_ptr[4];
    #pragma unroll
    for (int jj = 0; jj < 4; ++jj) {
        int idx = jj * 32 + lane;
        st_ptr[jj] = s_A + (idx >> 3) * A_STRIDE + (idx & 7) * 8;
    }

    float2 bv[8];
    #pragma unroll
    for (int ft = 0; ft < 8; ++ft) {
        bv[ft].x = bias[ft * 8 + la * 2 + 0];
        bv[ft].y = bias[ft * 8 + la * 2 + 1];
    }

    int gw = blockIdx.x * GWARPS + w;
    const int NWARP = gridDim.x * GWARPS;

    uint4 pf[4];
    if (gw < MM) {
        const uint4* src = (const uint4*)(g_buf16[0] + (size_t)gw * FTOT);
        #pragma unroll
        for (int jj = 0; jj < 4; ++jj) pf[jj] = src[jj * 32 + lane];
    }

    for (int m = gw; m < MM; m += NWARP) {
        float c[8][4];
        #pragma unroll
        for (int ft = 0; ft < 8; ++ft)
            c[ft][0] = c[ft][1] = c[ft][2] = c[ft][3] = 0.f;

        #pragma unroll
        for (int k = 0; k < KK; ++k) {
            #pragma unroll
            for (int jj = 0; jj < 4; ++jj)
                *(uint4*)st_ptr[jj] = pf[jj];
            __syncwarp();

            // prefetch next term / next m's term 0
            if (k < KK - 1) {
                const uint4* src = (const uint4*)(g_buf16[k + 1] + (size_t)m * FTOT);
                #pragma unroll
                for (int jj = 0; jj < 4; ++jj) pf[jj] = src[jj * 32 + lane];
            } else {
                int mn = m + NWARP;
                if (mn < MM) {
                    const uint4* src = (const uint4*)(g_buf16[0] + (size_t)mn * FTOT);
                    #pragma unroll
                    for (int jj = 0; jj < 4; ++jj) pf[jj] = src[jj * 32 + lane];
                }
            }

            #pragma unroll
            for (int fc = 0; fc < 4; ++fc) {
                uint32_t a0, a1, a2, a3;
                ldsm_x4(a0, a1, a2, a3, a_base + fc * 32);  // fc*16 halves
                const uint32_t* wb = s_W + ((k * 4 + fc) * 8) * 64 + lane * 2;
                #pragma unroll
                for (int ft = 0; ft < 8; ++ft) {
                    uint2 b = *(const uint2*)(wb + ft * 64);
                    mma_f16(c[ft], a0, a1, a2, a3, b.x, b.y);
                }
            }
            __syncwarp();
        }

        float* o0 = out + ((size_t)g * MM + m) * 64 + la * 2;
        float* o1 = out + ((size_t)(g + 8) * MM + m) * 64 + la * 2;
        #pragma unroll
        for (int ft = 0; ft < 8; ++ft) {
            float2 v0, v1;
            v0.x = c[ft][0] + bv[ft].x;
            v0.y = c[ft][1] + bv[ft].y;
            v1.x = c[ft][2] + bv[ft].x;
            v1.y = c[ft][3] + bv[ft].y;
            *(float2*)(o0 + ft * 8) = v0;
            *(float2*)(o1 + ft * 8) = v1;
        }
    }
}

// ---------------- launch ----------------
extern "C" void kernel_launch(void* const* d_in, const int* in_sizes, int n_in,
                              void* d_out, int out_size) {
    const float* x      = (const float*)d_in[0];
    const float* L_vals = (const float*)d_in[1];
    const float* weight = (const float*)d_in[2];
    const float* bias   = (const float*)d_in[3];
    const int*   L_rows = (const int*)d_in[4];
    const int*   L_cols = (const int*)d_in[5];
    float*       out    = (float*)d_out;

    (void)in_sizes; (void)n_in; (void)out_size;

    zero_cnt_kernel<<<(MM + 255) / 256, 256>>>();
    count_kernel<<<(NNZC + 255) / 256, 256>>>(L_rows);
    scan_kernel<<<1, 1024>>>();
    scatter_kernel<<<(NNZC + 255) / 256, 256>>>(L_rows, L_cols, L_vals);

    prep_w_kernel<<<24, 256>>>(weight);

    x0_kernel<<<MM, 128>>>(x);
    term_kernel<<<MM, 128>>>(0, 1, -1);
    term_kernel<<<MM, 128>>>(1, 2, 0);
    term_kernel<<<MM, 128>>>(2, 3, 1);
    term_kernel<<<MM, 128>>>(3, 4, 2);
    term_kernel<<<MM, 128>>>(4, 5, 3);

    cudaFuncSetAttribute(gemm_kernel, cudaFuncAttributeMaxDynamicSharedMemorySize,
                         SMEM_TOTAL);
    gemm_kernel<<<296, GWARPS * 32, SMEM_TOTAL>>>(bias, out);
}